// round 16
// baseline (speedup 1.0000x reference)
#include <cuda_runtime.h>
#include <cuda_bf16.h>
#include <cstdint>

// Problem constants
#define Bc     4
#define Nc     6
#define CIN    256
#define Hc     16
#define Wc     44
#define Dd     59
#define COUT   64
#define HW     (Hc*Wc)            // 704
#define NPIX   (Bc*Nc*HW)         // 16896
#define XX     128
#define YY     128
#define ZZ     7
#define BEV_SIZE (Bc*COUT*YY*XX)  // 4194304

// Scratch (static device global: no allocation)
__device__ float g_feat[NPIX * COUT];   // (B,N,H*W,64) contiguous, ~4.3MB

// packed fp32x2 helpers (bev kernel)
#define PACK2S(d, v)       asm("mov.b64 %0, {%1, %1};" : "=l"(d) : "f"(v))
#define UNPACK2(lo, hi, s) asm("mov.b64 {%0, %1}, %2;" : "=f"(lo), "=f"(hi) : "l"(s))
#define FFMA2(acc, a, b)   asm("fma.rn.f32x2 %0, %1, %2, %0;" : "+l"(acc) : "l"(a), "l"(b))

// bf16 hi/lo split of two floats, packed along k: lower half = x0, upper = x1
__device__ __forceinline__ void bfsplit2(float x0, float x1, uint32_t& hi, uint32_t& lo) {
    asm("cvt.rn.bf16x2.f32 %0, %1, %2;" : "=r"(hi) : "f"(x1), "f"(x0));
    float h0 = __uint_as_float(hi << 16);
    float h1 = __uint_as_float(hi & 0xffff0000u);
    float r0 = x0 - h0, r1 = x1 - h1;
    asm("cvt.rn.bf16x2.f32 %0, %1, %2;" : "=r"(lo) : "f"(r1), "f"(r0));
}

#define MMA_BF16(d, a, b0, b1) \
    asm volatile("mma.sync.aligned.m16n8k16.row.col.f32.bf16.bf16.f32 " \
        "{%0,%1,%2,%3}, {%4,%5,%6,%7}, {%8,%9}, {%0,%1,%2,%3};" \
        : "+f"((d)[0]), "+f"((d)[1]), "+f"((d)[2]), "+f"((d)[3]) \
        : "r"((a)[0]), "r"((a)[1]), "r"((a)[2]), "r"((a)[3]), "r"(b0), "r"(b1))

// ---------------------------------------------------------------------------
// Kernel 1: bf16 3-pass mma.sync GEMM (R15 form, 512 threads / 16 warps).
// ---------------------------------------------------------------------------
#define TILE_M 128
#define KCH    32
#define NCH    (CIN/KCH)            // 8 chunks
#define SSTR   136                  // words per j-row
#define HWORDS (16*SSTR)            // 2176 words per tile (16 j-rows)
#define BUFW   (4*HWORDS)           // 8704 words per buffer

__global__ __launch_bounds__(512)
void gemm_mma(const float* __restrict__ img,
              const float* __restrict__ w,
              const float* __restrict__ bias,
              float* __restrict__ depth_out) {
    extern __shared__ uint32_t sm[];           // buf0 | buf1; later T
    __shared__ float sbias[128];
    __shared__ int   sgb[32];

    float* T = (float*)sm;                     // logits tile [128][129] (alias)

    const int tid  = threadIdx.x;
    const int wid  = tid >> 5;                 // 0..15
    const int lane = tid & 31;
    const int g    = lane >> 2;                // group id (0..7)
    const int tig  = lane & 3;                 // thread in group
    const int wr   = wid & 1;                  // pixel half (64)
    const int wc   = wid >> 1;                 // output strip of 16 (0..7)
    const int p0   = blockIdx.x * TILE_M;

    if (tid < 32) {
        int p = p0 + tid*4;                    // HW%4==0 -> group stays in one bn
        int bn = p / HW;
        sgb[tid] = bn*CIN*HW + (p - bn*HW);
    }
    if (tid < 128) sbias[tid] = (tid < 123) ? bias[tid] : 0.0f;
    __syncthreads();

    const int ob = tid & 127;                  // B-staging output row
    const int oq = tid >> 7;                   // B-staging k quarter (0..3)
    const float* wb = w + (size_t)ob*CIN + oq*8;

    float acc[4][2][4] = {};                   // [mt][nt][c-frag]
    float4 ra0, ra1, rb[2];                    // staged regs for one chunk
    const int agg = tid & 31, aj = tid >> 5;   // A staging coords (16x32 = 512)

    // ---- prefetch chunk 0 ----
    {
        const float* base = img + sgb[agg] + (size_t)(2*aj)*HW;
        ra0 = *(const float4*)base;
        ra1 = *(const float4*)(base + HW);
    }
    #pragma unroll
    for (int i = 0; i < 2; i++)
        rb[i] = (ob < 123) ? *(const float4*)(wb + 4*i)
                           : make_float4(0.f, 0.f, 0.f, 0.f);

    for (int ch = 0; ch < NCH; ch++) {
        uint32_t* buf = sm + (ch & 1)*BUFW;
        uint32_t* aHi = buf;
        uint32_t* aLo = buf + HWORDS;
        uint32_t* bHi = buf + 2*HWORDS;
        uint32_t* bLo = buf + 3*HWORDS;

        // ---- store staged chunk ch (convert + STS) ----
        {
            uint32_t h[4], l[4];
            bfsplit2(ra0.x, ra1.x, h[0], l[0]);
            bfsplit2(ra0.y, ra1.y, h[1], l[1]);
            bfsplit2(ra0.z, ra1.z, h[2], l[2]);
            bfsplit2(ra0.w, ra1.w, h[3], l[3]);
            *(uint4*)&aHi[aj*SSTR + 4*agg] = make_uint4(h[0], h[1], h[2], h[3]);
            *(uint4*)&aLo[aj*SSTR + 4*agg] = make_uint4(l[0], l[1], l[2], l[3]);
        }
        #pragma unroll
        for (int i = 0; i < 2; i++) {
            int kg = oq*2 + i;                 // k-quad 0..7 -> j rows 2kg,2kg+1
            uint32_t h0, l0, h1, l1;
            bfsplit2(rb[i].x, rb[i].y, h0, l0);
            bfsplit2(rb[i].z, rb[i].w, h1, l1);
            bHi[(2*kg  )*SSTR + ob] = h0;
            bHi[(2*kg+1)*SSTR + ob] = h1;
            bLo[(2*kg  )*SSTR + ob] = l0;
            bLo[(2*kg+1)*SSTR + ob] = l1;
        }
        __syncthreads();

        // ---- prefetch chunk ch+1 (LDGs overlap the mma below) ----
        if (ch + 1 < NCH) {
            const int kc = (ch + 1)*KCH;
            const float* base = img + sgb[agg] + (size_t)(kc + 2*aj)*HW;
            ra0 = *(const float4*)base;
            ra1 = *(const float4*)(base + HW);
            #pragma unroll
            for (int i = 0; i < 2; i++)
                rb[i] = (ob < 123) ? *(const float4*)(wb + kc + 4*i)
                                   : make_float4(0.f, 0.f, 0.f, 0.f);
        }

        // ---- mma on chunk ch: per kstep, operands loaded once & reused ----
        #pragma unroll
        for (int ks = 0; ks < 2; ks++) {
            const int j0 = ks*8;
            uint32_t ah[4][4], al[4][4], bh[2][2], bl[2][2];
            #pragma unroll
            for (int mt = 0; mt < 4; mt++) {
                int m0 = wr*64 + mt*16;
                ah[mt][0] = aHi[(j0+tig  )*SSTR + m0 + g    ];
                ah[mt][1] = aHi[(j0+tig  )*SSTR + m0 + g + 8];
                ah[mt][2] = aHi[(j0+tig+4)*SSTR + m0 + g    ];
                ah[mt][3] = aHi[(j0+tig+4)*SSTR + m0 + g + 8];
            }
            #pragma unroll
            for (int nt = 0; nt < 2; nt++) {
                int n0 = wc*16 + nt*8;
                bh[nt][0] = bHi[(j0+tig  )*SSTR + n0 + g];
                bh[nt][1] = bHi[(j0+tig+4)*SSTR + n0 + g];
            }
            #pragma unroll
            for (int nt = 0; nt < 2; nt++)
                #pragma unroll
                for (int mt = 0; mt < 4; mt++)
                    MMA_BF16(acc[mt][nt], ah[mt], bh[nt][0], bh[nt][1]);
            #pragma unroll
            for (int nt = 0; nt < 2; nt++) {
                int n0 = wc*16 + nt*8;
                bl[nt][0] = bLo[(j0+tig  )*SSTR + n0 + g];
                bl[nt][1] = bLo[(j0+tig+4)*SSTR + n0 + g];
            }
            #pragma unroll
            for (int nt = 0; nt < 2; nt++)
                #pragma unroll
                for (int mt = 0; mt < 4; mt++)
                    MMA_BF16(acc[mt][nt], ah[mt], bl[nt][0], bl[nt][1]);
            #pragma unroll
            for (int mt = 0; mt < 4; mt++) {
                int m0 = wr*64 + mt*16;
                al[mt][0] = aLo[(j0+tig  )*SSTR + m0 + g    ];
                al[mt][1] = aLo[(j0+tig  )*SSTR + m0 + g + 8];
                al[mt][2] = aLo[(j0+tig+4)*SSTR + m0 + g    ];
                al[mt][3] = aLo[(j0+tig+4)*SSTR + m0 + g + 8];
            }
            #pragma unroll
            for (int nt = 0; nt < 2; nt++)
                #pragma unroll
                for (int mt = 0; mt < 4; mt++)
                    MMA_BF16(acc[mt][nt], al[mt], bh[nt][0], bh[nt][1]);
        }
    }
    __syncthreads();   // all mma reads done before T aliases the buffers

    // ---- Epilogue: acc -> T[pix][129] with bias ----
    #pragma unroll
    for (int mt = 0; mt < 4; mt++) {
        #pragma unroll
        for (int nt = 0; nt < 2; nt++) {
            int row0 = wr*64 + mt*16 + g;
            int col  = wc*16 + nt*8 + 2*tig;
            T[ row0   *129 + col    ] = acc[mt][nt][0] + sbias[col];
            T[ row0   *129 + col + 1] = acc[mt][nt][1] + sbias[col+1];
            T[(row0+8)*129 + col    ] = acc[mt][nt][2] + sbias[col];
            T[(row0+8)*129 + col + 1] = acc[mt][nt][3] + sbias[col+1];
        }
    }
    __syncthreads();

    // Fused softmax + depth write: warp owns 8 pixels, all in registers.
    #pragma unroll
    for (int i = 0; i < 8; i++) {
        int p = wid*8 + i;
        float v0 = (lane      < Dd) ? T[p*129 + lane]      : -3.4e38f;
        float v1 = (lane + 32 < Dd) ? T[p*129 + lane + 32] : -3.4e38f;
        float mx = fmaxf(v0, v1);
        #pragma unroll
        for (int o = 16; o; o >>= 1) mx = fmaxf(mx, __shfl_xor_sync(~0u, mx, o));
        float e0 = (lane      < Dd) ? expf(v0 - mx) : 0.0f;
        float e1 = (lane + 32 < Dd) ? expf(v1 - mx) : 0.0f;
        float s = e0 + e1;
        #pragma unroll
        for (int o = 16; o; o >>= 1) s += __shfl_xor_sync(~0u, s, o);
        float inv = 1.0f / s;                   // all lanes hold the result
        float* dp = depth_out + (size_t)(p0 + p)*Dd;
        if (lane      < Dd) dp[lane]      = e0 * inv;
        if (lane + 32 < Dd) dp[lane + 32] = e1 * inv;
    }

    for (int i = tid; i < TILE_M*COUT; i += 512) {
        int pix = i >> 6;
        int c   = i & 63;
        g_feat[(size_t)(p0 + pix)*COUT + c] = T[pix*129 + Dd + c];
    }
}

// ---------------------------------------------------------------------------
// Kernel 2: voxel projection + splat, PDL-overlapped.
//  A1: projection -> (validflag, packed pp*64+db) — no reads of gemm output.
//  Compaction (ballot) on the flag. Then cudaGridDependencySynchronize().
//  A2: batched depth gather over compacted entries (flag->wgt, packed->off).
//  Phase B: half-warp per x, 4 channels per lane, MLP=4 body (R13 form).
// ---------------------------------------------------------------------------
#define XQ 32     // x values per block
#define SLP 46    // padded sl row stride (entries)
#define SACCP 68  // sacc row stride (floats)

__global__ __launch_bounds__(256)
void bev_kernel(const float* __restrict__ c2e,
                const float* __restrict__ Kin,
                const float* __restrict__ depth,
                float* __restrict__ bev) {
    __shared__ float2 sl[XQ*SLP];       // [x][s] (wgt/flag, packed/off)
    __shared__ float  sacc[XQ*SACCP];   // [x][c]
    __shared__ int    scnt[XQ];
    __shared__ float  sbase[Nc][ZZ][3];
    __shared__ float  scol0[Nc][4];
    __shared__ float  sK[Nc][4];

    const int blk = blockIdx.x;
    const int xq  = blk & 3;
    const int y   = (blk >> 2) & 127;
    const int b   = blk >> 9;
    const int tid = threadIdx.x;
    const float py = y*0.8f - 51.2f;

    if (tid < Nc*ZZ) {
        int n = tid / ZZ, z = tid - n*ZZ;
        const float* m = c2e + (b*Nc + n)*16;   // cam2ego 4x4
        float pz = (float)z - 2.5f;
        #pragma unroll
        for (int i = 0; i < 3; i++) {
            float e1 = m[4+i], e2 = m[8+i];
            float e3 = -(m[i]*m[3] + e1*m[7] + e2*m[11]);
            sbase[n][z][i] = py*e1 + pz*e2 + e3;
        }
        if (z == 0) {
            scol0[n][0] = m[0]; scol0[n][1] = m[1]; scol0[n][2] = m[2];
            const float* k = Kin + (b*Nc + n)*9;
            sK[n][0] = k[0]; sK[n][1] = k[4]; sK[n][2] = k[2]; sK[n][3] = k[5];
        }
    }
    __syncthreads();

    // ---- Phase A1: projections only (no gemm-output reads) ----
    #pragma unroll
    for (int r = 0; r < 6; r++) {
        int idx = tid + 256*r;
        if (idx < Nc*ZZ*XQ) {
            int x = idx & (XQ-1);
            int s = idx >> 5;          // 0..41 (warp-uniform)
            int n = s / ZZ;
            int z = s - n*ZZ;
            float px = (float)(xq*XQ + x)*0.8f - 51.2f;
            float camx = px*scol0[n][0] + sbase[n][z][0];
            float camy = px*scol0[n][1] + sbase[n][z][1];
            float camz = px*scol0[n][2] + sbase[n][z][2];
            float rz   = 1.0f / fmaxf(camz, 0.1f);
            float fu   = (sK[n][0]*(camx*rz) + sK[n][2]) * 0.0625f;
            float fv   = (sK[n][1]*(camy*rz) + sK[n][3]) * 0.0625f;
            int   db   = (int)(camz - 1.0f);   // trunc == numpy astype(int32)
            bool valid = (fu >= 0.0f) && (fu < (float)Wc) &&
                         (fv >= 0.0f) && (fv < (float)Hc) &&
                         (camz > 0.5f) && (db >= 0) && (db < Dd);
            float flag = 0.0f;
            int   packed = 0;
            if (valid) {
                int u = (int)fu;
                int v = (int)fv;
                int pp = (b*Nc + n)*HW + v*Wc + u;
                packed = pp*64 + db;           // pp = packed>>6, db = packed&63
                flag = 1.0f;
            }
            sl[x*SLP + s] = make_float2(flag, __int_as_float(packed));
        }
    }
    __syncthreads();

    const int warp = tid >> 5;
    const int lane = tid & 31;
    const unsigned lmlt = (1u << lane) - 1u;

    // ---- Compaction: warp per 4 rows, ballot prefix, pad to mult of 4 ----
    #pragma unroll
    for (int xr = 0; xr < 4; xr++) {
        int x = warp*4 + xr;
        float2* row = &sl[x*SLP];
        float2 e0 = row[lane];
        unsigned m0 = __ballot_sync(~0u, e0.x != 0.0f);
        if (e0.x != 0.0f) row[__popc(m0 & lmlt)] = e0;
        int c0 = __popc(m0);
        bool a1 = lane < 10;
        float2 e1 = a1 ? row[32 + lane] : make_float2(0.f, 0.f);
        unsigned m1 = __ballot_sync(~0u, a1 && e1.x != 0.0f);
        if (a1 && e1.x != 0.0f) row[c0 + __popc(m1 & lmlt)] = e1;
        int c = c0 + __popc(m1);
        int cp = (c + 3) & ~3;                  // <= 44 < SLP
        if (lane < cp - c) row[c + lane] = make_float2(0.f, 0.f);
        if (lane == 0) scnt[x] = cp;
    }
    __syncthreads();

    // ---- wait for gemm grid (PDL) before reading depth / g_feat ----
    cudaGridDependencySynchronize();

    // ---- Phase A2: batched depth gather over compacted entries ----
    for (int i = tid; i < XQ*44; i += 256) {
        int x = i / 44;
        int j = i - x*44;
        if (j < scnt[x]) {
            float2 e = sl[x*SLP + j];
            if (e.x != 0.0f) {
                int packed = __float_as_int(e.y);
                float wgt = depth[(size_t)(packed >> 6)*Dd + (packed & 63)];
                sl[x*SLP + j] = make_float2(wgt, __int_as_float(packed & ~63));
            }
        }
    }
    __syncthreads();

    // ---- Phase B: half-warp per x, 4 channels per lane, MLP=4 body ----
    const int xi = lane >> 4;          // which x of the pair
    const int cl = lane & 15;          // channel group: c = 4*cl .. 4*cl+3
    const float* fb = g_feat + cl*4;

    #pragma unroll
    for (int it = 0; it < 2; it++) {
        const int x = warp*4 + it*2 + xi;
        const int cnt = scnt[x];                // padded multiple of 4
        const float2* row = &sl[x*SLP];
        uint64_t acc0 = 0, acc1 = 0;            // packed {4cl,4cl+1}, {4cl+2,4cl+3}
        for (int j = 0; j < cnt; j += 4) {
            float4 e0 = *(const float4*)(row + j);       // entries j, j+1
            float4 e1 = *(const float4*)(row + j + 2);   // entries j+2, j+3
            ulonglong2 f0 = *(const ulonglong2*)(fb + __float_as_int(e0.y));
            ulonglong2 f1 = *(const ulonglong2*)(fb + __float_as_int(e0.w));
            ulonglong2 f2 = *(const ulonglong2*)(fb + __float_as_int(e1.y));
            ulonglong2 f3 = *(const ulonglong2*)(fb + __float_as_int(e1.w));
            uint64_t p0, p1, p2, p3;
            PACK2S(p0, e0.x); PACK2S(p1, e0.z);
            PACK2S(p2, e1.x); PACK2S(p3, e1.z);
            FFMA2(acc0, p0, f0.x); FFMA2(acc1, p0, f0.y);
            FFMA2(acc0, p1, f1.x); FFMA2(acc1, p1, f1.y);
            FFMA2(acc0, p2, f2.x); FFMA2(acc1, p2, f2.y);
            FFMA2(acc0, p3, f3.x); FFMA2(acc1, p3, f3.y);
        }
        float c0, c1, c2, c3;
        UNPACK2(c0, c1, acc0);
        UNPACK2(c2, c3, acc1);
        *(float4*)&sacc[x*SACCP + cl*4] = make_float4(c0, c1, c2, c3);
    }
    __syncthreads();

    // bev[b, c, y, x] — 32-wide contiguous segments
    #pragma unroll
    for (int r = 0; r < 8; r++) {
        int i = tid + 256*r;
        int c = i >> 5;
        int x = i & 31;
        bev[(((size_t)b*COUT + c)*YY + y)*XX + xq*XQ + x] = sacc[x*SACCP + c];
    }
}

// ---------------------------------------------------------------------------
extern "C" void kernel_launch(void* const* d_in, const int* in_sizes, int n_in,
                              void* d_out, int out_size) {
    const float* img  = (const float*)d_in[0];  // (4,6,256,16,44)
    const float* c2e  = (const float*)d_in[1];  // (4,6,4,4)
    const float* Kin  = (const float*)d_in[2];  // (4,6,3,3)
    const float* w    = (const float*)d_in[3];  // (123,256)
    const float* bias = (const float*)d_in[4];  // (123,)
    float* out       = (float*)d_out;
    float* depth_out = out + BEV_SIZE;          // outputs: [bev | depth]

    const int smem_bytes = 2*BUFW*4;            // 69632 B
    cudaFuncSetAttribute(gemm_mma, cudaFuncAttributeMaxDynamicSharedMemorySize, smem_bytes);

    gemm_mma<<<NPIX/TILE_M, 512, smem_bytes>>>(img, w, bias, depth_out);

    // bev with programmatic dependent launch: starts while gemm drains; its
    // cudaGridDependencySynchronize() gates all reads of gemm output.
    cudaLaunchConfig_t cfg = {};
    cfg.gridDim  = dim3(Bc*YY*4);
    cfg.blockDim = dim3(256);
    cfg.dynamicSmemBytes = 0;
    cfg.stream = 0;
    cudaLaunchAttribute attr[1];
    attr[0].id = cudaLaunchAttributeProgrammaticStreamSerialization;
    attr[0].val.programmaticStreamSerializationAllowed = 1;
    cfg.attrs = attr;
    cfg.numAttrs = 1;
    cudaLaunchKernelEx(&cfg, bev_kernel, c2e, Kin, depth_out, out);
}

// round 17
// speedup vs baseline: 1.1268x; 1.1268x over previous
#include <cuda_runtime.h>
#include <cuda_bf16.h>
#include <cstdint>

// Problem constants
#define Bc     4
#define Nc     6
#define CIN    256
#define Hc     16
#define Wc     44
#define Dd     59
#define COUT   64
#define HW     (Hc*Wc)            // 704
#define NPIX   (Bc*Nc*HW)         // 16896
#define XX     128
#define YY     128
#define ZZ     7
#define BEV_SIZE (Bc*COUT*YY*XX)  // 4194304

// Scratch (static device global: no allocation)
__device__ float g_feat[NPIX * COUT];   // (B,N,H*W,64) contiguous, ~4.3MB

// packed fp32x2 helpers (bev kernel)
#define PACK2S(d, v)       asm("mov.b64 %0, {%1, %1};" : "=l"(d) : "f"(v))
#define UNPACK2(lo, hi, s) asm("mov.b64 {%0, %1}, %2;" : "=f"(lo), "=f"(hi) : "l"(s))
#define FFMA2(acc, a, b)   asm("fma.rn.f32x2 %0, %1, %2, %0;" : "+l"(acc) : "l"(a), "l"(b))

// bf16 hi/lo split of two floats, packed along k: lower half = x0, upper = x1
__device__ __forceinline__ void bfsplit2(float x0, float x1, uint32_t& hi, uint32_t& lo) {
    asm("cvt.rn.bf16x2.f32 %0, %1, %2;" : "=r"(hi) : "f"(x1), "f"(x0));
    float h0 = __uint_as_float(hi << 16);
    float h1 = __uint_as_float(hi & 0xffff0000u);
    float r0 = x0 - h0, r1 = x1 - h1;
    asm("cvt.rn.bf16x2.f32 %0, %1, %2;" : "=r"(lo) : "f"(r1), "f"(r0));
}

#define MMA_BF16(d, a, b0, b1) \
    asm volatile("mma.sync.aligned.m16n8k16.row.col.f32.bf16.bf16.f32 " \
        "{%0,%1,%2,%3}, {%4,%5,%6,%7}, {%8,%9}, {%0,%1,%2,%3};" \
        : "+f"((d)[0]), "+f"((d)[1]), "+f"((d)[2]), "+f"((d)[3]) \
        : "r"((a)[0]), "r"((a)[1]), "r"((a)[2]), "r"((a)[3]), "r"(b0), "r"(b1))

// ---------------------------------------------------------------------------
// Kernel 1: bf16 3-pass mma.sync GEMM (128 pix x 128 out, K=256) + bias +
// softmax(59) + split. 512 threads = 16 warps (4/SMSP), warp tile 64 x 16.
// Double-buffered K-chunks of 64 (4 chunks, 4 barriers); per-kstep operand
// reuse: Ah{Bh,Bl} then {Al}Bh.  D = Ah*Bh + Ah*Bl + Al*Bh  (error ~2^-16).
// ---------------------------------------------------------------------------
#define TILE_M 128
#define KCH    64
#define NCH    (CIN/KCH)            // 4 chunks
#define SSTR   136                  // words per j-row
#define HWORDS (32*SSTR)            // 4352 words per tile (32 j-rows)
#define BUFW   (4*HWORDS)           // 17408 words per buffer

__global__ __launch_bounds__(512)
void gemm_mma(const float* __restrict__ img,
              const float* __restrict__ w,
              const float* __restrict__ bias,
              float* __restrict__ depth_out) {
    extern __shared__ uint32_t sm[];           // buf0 | buf1; later T
    __shared__ float sbias[128];
    __shared__ int   sgb[32];

    float* T = (float*)sm;                     // logits tile [128][129] (alias)

    const int tid  = threadIdx.x;
    const int wid  = tid >> 5;                 // 0..15
    const int lane = tid & 31;
    const int g    = lane >> 2;                // group id (0..7)
    const int tig  = lane & 3;                 // thread in group
    const int wr   = wid & 1;                  // pixel half (64)
    const int wc   = wid >> 1;                 // output strip of 16 (0..7)
    const int p0   = blockIdx.x * TILE_M;

    if (tid < 32) {
        int p = p0 + tid*4;                    // HW%4==0 -> group stays in one bn
        int bn = p / HW;
        sgb[tid] = bn*CIN*HW + (p - bn*HW);
    }
    if (tid < 128) sbias[tid] = (tid < 123) ? bias[tid] : 0.0f;
    __syncthreads();

    const int ob = tid & 127;                  // B-staging output row
    const int oq = tid >> 7;                   // B-staging k quarter (0..3)
    const float* wb = w + (size_t)ob*CIN + oq*16;

    float acc[4][2][4] = {};                   // [mt][nt][c-frag]
    float4 ra0[2], ra1[2], rb[4];              // staged regs for one chunk
    const int agg = tid & 31;                  // A staging pixel group
    const int aj0 = tid >> 5;                  // A staging j base (0..15)

    // ---- prefetch chunk 0 ----
    #pragma unroll
    for (int r = 0; r < 2; r++) {
        int aj = aj0 + 16*r;
        const float* base = img + sgb[agg] + (size_t)(2*aj)*HW;
        ra0[r] = *(const float4*)base;
        ra1[r] = *(const float4*)(base + HW);
    }
    #pragma unroll
    for (int i = 0; i < 4; i++)
        rb[i] = (ob < 123) ? *(const float4*)(wb + 4*i)
                           : make_float4(0.f, 0.f, 0.f, 0.f);

    for (int ch = 0; ch < NCH; ch++) {
        uint32_t* buf = sm + (ch & 1)*BUFW;
        uint32_t* aHi = buf;
        uint32_t* aLo = buf + HWORDS;
        uint32_t* bHi = buf + 2*HWORDS;
        uint32_t* bLo = buf + 3*HWORDS;

        // ---- store staged chunk ch (convert + STS) ----
        #pragma unroll
        for (int r = 0; r < 2; r++) {
            int aj = aj0 + 16*r;
            uint32_t h[4], l[4];
            bfsplit2(ra0[r].x, ra1[r].x, h[0], l[0]);
            bfsplit2(ra0[r].y, ra1[r].y, h[1], l[1]);
            bfsplit2(ra0[r].z, ra1[r].z, h[2], l[2]);
            bfsplit2(ra0[r].w, ra1[r].w, h[3], l[3]);
            *(uint4*)&aHi[aj*SSTR + 4*agg] = make_uint4(h[0], h[1], h[2], h[3]);
            *(uint4*)&aLo[aj*SSTR + 4*agg] = make_uint4(l[0], l[1], l[2], l[3]);
        }
        #pragma unroll
        for (int i = 0; i < 4; i++) {
            int kg = oq*4 + i;                 // k-quad 0..15 -> j rows 2kg,2kg+1
            uint32_t h0, l0, h1, l1;
            bfsplit2(rb[i].x, rb[i].y, h0, l0);
            bfsplit2(rb[i].z, rb[i].w, h1, l1);
            bHi[(2*kg  )*SSTR + ob] = h0;
            bHi[(2*kg+1)*SSTR + ob] = h1;
            bLo[(2*kg  )*SSTR + ob] = l0;
            bLo[(2*kg+1)*SSTR + ob] = l1;
        }
        __syncthreads();

        // ---- prefetch chunk ch+1 (LDGs overlap the mma below) ----
        if (ch + 1 < NCH) {
            const int kc = (ch + 1)*KCH;
            #pragma unroll
            for (int r = 0; r < 2; r++) {
                int aj = aj0 + 16*r;
                const float* base = img + sgb[agg] + (size_t)(kc + 2*aj)*HW;
                ra0[r] = *(const float4*)base;
                ra1[r] = *(const float4*)(base + HW);
            }
            #pragma unroll
            for (int i = 0; i < 4; i++)
                rb[i] = (ob < 123) ? *(const float4*)(wb + kc + 4*i)
                                   : make_float4(0.f, 0.f, 0.f, 0.f);
        }

        // ---- mma on chunk ch: per kstep, operands loaded once & reused ----
        #pragma unroll
        for (int ks = 0; ks < 4; ks++) {
            const int j0 = ks*8;
            uint32_t ah[4][4], al[4][4], bh[2][2], bl[2][2];
            #pragma unroll
            for (int mt = 0; mt < 4; mt++) {
                int m0 = wr*64 + mt*16;
                ah[mt][0] = aHi[(j0+tig  )*SSTR + m0 + g    ];
                ah[mt][1] = aHi[(j0+tig  )*SSTR + m0 + g + 8];
                ah[mt][2] = aHi[(j0+tig+4)*SSTR + m0 + g    ];
                ah[mt][3] = aHi[(j0+tig+4)*SSTR + m0 + g + 8];
            }
            #pragma unroll
            for (int nt = 0; nt < 2; nt++) {
                int n0 = wc*16 + nt*8;
                bh[nt][0] = bHi[(j0+tig  )*SSTR + n0 + g];
                bh[nt][1] = bHi[(j0+tig+4)*SSTR + n0 + g];
            }
            #pragma unroll
            for (int nt = 0; nt < 2; nt++)
                #pragma unroll
                for (int mt = 0; mt < 4; mt++)
                    MMA_BF16(acc[mt][nt], ah[mt], bh[nt][0], bh[nt][1]);
            #pragma unroll
            for (int nt = 0; nt < 2; nt++) {
                int n0 = wc*16 + nt*8;
                bl[nt][0] = bLo[(j0+tig  )*SSTR + n0 + g];
                bl[nt][1] = bLo[(j0+tig+4)*SSTR + n0 + g];
            }
            #pragma unroll
            for (int nt = 0; nt < 2; nt++)
                #pragma unroll
                for (int mt = 0; mt < 4; mt++)
                    MMA_BF16(acc[mt][nt], ah[mt], bl[nt][0], bl[nt][1]);
            #pragma unroll
            for (int mt = 0; mt < 4; mt++) {
                int m0 = wr*64 + mt*16;
                al[mt][0] = aLo[(j0+tig  )*SSTR + m0 + g    ];
                al[mt][1] = aLo[(j0+tig  )*SSTR + m0 + g + 8];
                al[mt][2] = aLo[(j0+tig+4)*SSTR + m0 + g    ];
                al[mt][3] = aLo[(j0+tig+4)*SSTR + m0 + g + 8];
            }
            #pragma unroll
            for (int nt = 0; nt < 2; nt++)
                #pragma unroll
                for (int mt = 0; mt < 4; mt++)
                    MMA_BF16(acc[mt][nt], al[mt], bh[nt][0], bh[nt][1]);
        }
        // next store targets the other buffer; same-buffer reuse is separated
        // by the sync at the top of the next iteration.
    }
    __syncthreads();   // all mma reads done before T aliases the buffers

    // ---- Epilogue: acc -> T[pix][129] with bias ----
    #pragma unroll
    for (int mt = 0; mt < 4; mt++) {
        #pragma unroll
        for (int nt = 0; nt < 2; nt++) {
            int row0 = wr*64 + mt*16 + g;
            int col  = wc*16 + nt*8 + 2*tig;
            T[ row0   *129 + col    ] = acc[mt][nt][0] + sbias[col];
            T[ row0   *129 + col + 1] = acc[mt][nt][1] + sbias[col+1];
            T[(row0+8)*129 + col    ] = acc[mt][nt][2] + sbias[col];
            T[(row0+8)*129 + col + 1] = acc[mt][nt][3] + sbias[col+1];
        }
    }
    __syncthreads();

    // Fused softmax + depth write: warp owns 8 pixels, all in registers.
    #pragma unroll
    for (int i = 0; i < 8; i++) {
        int p = wid*8 + i;
        float v0 = (lane      < Dd) ? T[p*129 + lane]      : -3.4e38f;
        float v1 = (lane + 32 < Dd) ? T[p*129 + lane + 32] : -3.4e38f;
        float mx = fmaxf(v0, v1);
        #pragma unroll
        for (int o = 16; o; o >>= 1) mx = fmaxf(mx, __shfl_xor_sync(~0u, mx, o));
        float e0 = (lane      < Dd) ? expf(v0 - mx) : 0.0f;
        float e1 = (lane + 32 < Dd) ? expf(v1 - mx) : 0.0f;
        float s = e0 + e1;
        #pragma unroll
        for (int o = 16; o; o >>= 1) s += __shfl_xor_sync(~0u, s, o);
        float inv = 1.0f / s;                   // all lanes hold the result
        float* dp = depth_out + (size_t)(p0 + p)*Dd;
        if (lane      < Dd) dp[lane]      = e0 * inv;
        if (lane + 32 < Dd) dp[lane + 32] = e1 * inv;
    }

    for (int i = tid; i < TILE_M*COUT; i += 512) {
        int pix = i >> 6;
        int c   = i & 63;
        g_feat[(size_t)(p0 + pix)*COUT + c] = T[pix*129 + Dd + c];
    }
}

// ---------------------------------------------------------------------------
// Kernel 2: voxel projection + depth-weighted feature splat (R15/R13 form —
// measured best 25.9-26.2us: ballot compaction + padded MLP=4 Phase B).
// ---------------------------------------------------------------------------
#define XQ 32     // x values per block
#define SLP 46    // padded sl row stride (entries)
#define SACCP 68  // sacc row stride (floats)

__global__ __launch_bounds__(256)
void bev_kernel(const float* __restrict__ c2e,
                const float* __restrict__ Kin,
                const float* __restrict__ depth,
                float* __restrict__ bev) {
    __shared__ float2 sl[XQ*SLP];       // [x][s] (wgt, feat_off_as_float)
    __shared__ float  sacc[XQ*SACCP];   // [x][c]
    __shared__ int    scnt[XQ];
    __shared__ float  sbase[Nc][ZZ][3];
    __shared__ float  scol0[Nc][4];
    __shared__ float  sK[Nc][4];

    const int blk = blockIdx.x;
    const int xq  = blk & 3;
    const int y   = (blk >> 2) & 127;
    const int b   = blk >> 9;
    const int tid = threadIdx.x;
    const float py = y*0.8f - 51.2f;

    if (tid < Nc*ZZ) {
        int n = tid / ZZ, z = tid - n*ZZ;
        const float* m = c2e + (b*Nc + n)*16;   // cam2ego 4x4
        float pz = (float)z - 2.5f;
        #pragma unroll
        for (int i = 0; i < 3; i++) {
            float e1 = m[4+i], e2 = m[8+i];
            float e3 = -(m[i]*m[3] + e1*m[7] + e2*m[11]);
            sbase[n][z][i] = py*e1 + pz*e2 + e3;
        }
        if (z == 0) {
            scol0[n][0] = m[0]; scol0[n][1] = m[1]; scol0[n][2] = m[2];
            const float* k = Kin + (b*Nc + n)*9;
            sK[n][0] = k[0]; sK[n][1] = k[4]; sK[n][2] = k[2]; sK[n][3] = k[5];
        }
    }
    __syncthreads();

    // ---- Phase A: per-lane projections (42 samples x 32 x = 1344) ----
    #pragma unroll
    for (int r = 0; r < 6; r++) {
        int idx = tid + 256*r;
        if (idx < Nc*ZZ*XQ) {
            int x = idx & (XQ-1);
            int s = idx >> 5;          // 0..41 (warp-uniform)
            int n = s / ZZ;
            int z = s - n*ZZ;
            float px = (float)(xq*XQ + x)*0.8f - 51.2f;
            float camx = px*scol0[n][0] + sbase[n][z][0];
            float camy = px*scol0[n][1] + sbase[n][z][1];
            float camz = px*scol0[n][2] + sbase[n][z][2];
            float rz   = 1.0f / fmaxf(camz, 0.1f);
            float fu   = (sK[n][0]*(camx*rz) + sK[n][2]) * 0.0625f;
            float fv   = (sK[n][1]*(camy*rz) + sK[n][3]) * 0.0625f;
            int   db   = (int)(camz - 1.0f);   // trunc == numpy astype(int32)
            bool valid = (fu >= 0.0f) && (fu < (float)Wc) &&
                         (fv >= 0.0f) && (fv < (float)Hc) &&
                         (camz > 0.5f) && (db >= 0) && (db < Dd);
            float wgt = 0.0f;
            int   off = 0;
            if (valid) {
                int u = (int)fu;
                int v = (int)fv;
                int pp = (b*Nc + n)*HW + v*Wc + u;
                wgt = depth[(size_t)pp*Dd + db];
                off = pp*COUT;
            }
            sl[x*SLP + s] = make_float2(wgt, __int_as_float(off));
        }
    }
    __syncthreads();

    const int warp = tid >> 5;
    const int lane = tid & 31;
    const unsigned lmlt = (1u << lane) - 1u;

    // ---- Compaction: warp per 4 rows, ballot prefix, pad to mult of 4 ----
    #pragma unroll
    for (int xr = 0; xr < 4; xr++) {
        int x = warp*4 + xr;
        float2* row = &sl[x*SLP];
        float2 e0 = row[lane];
        unsigned m0 = __ballot_sync(~0u, e0.x != 0.0f);
        if (e0.x != 0.0f) row[__popc(m0 & lmlt)] = e0;
        int c0 = __popc(m0);
        bool a1 = lane < 10;
        float2 e1 = a1 ? row[32 + lane] : make_float2(0.f, 0.f);
        unsigned m1 = __ballot_sync(~0u, a1 && e1.x != 0.0f);
        if (a1 && e1.x != 0.0f) row[c0 + __popc(m1 & lmlt)] = e1;
        int c = c0 + __popc(m1);
        int cp = (c + 3) & ~3;                  // <= 44 < SLP
        if (lane < cp - c) row[c + lane] = make_float2(0.f, 0.f);
        if (lane == 0) scnt[x] = cp;
    }
    __syncthreads();

    // ---- Phase B: half-warp per x, 4 channels per lane, MLP=4 body ----
    const int xi = lane >> 4;          // which x of the pair
    const int cl = lane & 15;          // channel group: c = 4*cl .. 4*cl+3
    const float* fb = g_feat + cl*4;

    #pragma unroll
    for (int it = 0; it < 2; it++) {
        const int x = warp*4 + it*2 + xi;
        const int cnt = scnt[x];                // padded multiple of 4
        const float2* row = &sl[x*SLP];
        uint64_t acc0 = 0, acc1 = 0;            // packed {4cl,4cl+1}, {4cl+2,4cl+3}
        for (int j = 0; j < cnt; j += 4) {
            float4 e0 = *(const float4*)(row + j);       // entries j, j+1
            float4 e1 = *(const float4*)(row + j + 2);   // entries j+2, j+3
            ulonglong2 f0 = *(const ulonglong2*)(fb + __float_as_int(e0.y));
            ulonglong2 f1 = *(const ulonglong2*)(fb + __float_as_int(e0.w));
            ulonglong2 f2 = *(const ulonglong2*)(fb + __float_as_int(e1.y));
            ulonglong2 f3 = *(const ulonglong2*)(fb + __float_as_int(e1.w));
            uint64_t p0, p1, p2, p3;
            PACK2S(p0, e0.x); PACK2S(p1, e0.z);
            PACK2S(p2, e1.x); PACK2S(p3, e1.z);
            FFMA2(acc0, p0, f0.x); FFMA2(acc1, p0, f0.y);
            FFMA2(acc0, p1, f1.x); FFMA2(acc1, p1, f1.y);
            FFMA2(acc0, p2, f2.x); FFMA2(acc1, p2, f2.y);
            FFMA2(acc0, p3, f3.x); FFMA2(acc1, p3, f3.y);
        }
        float c0, c1, c2, c3;
        UNPACK2(c0, c1, acc0);
        UNPACK2(c2, c3, acc1);
        *(float4*)&sacc[x*SACCP + cl*4] = make_float4(c0, c1, c2, c3);
    }
    __syncthreads();

    // bev[b, c, y, x] — 32-wide contiguous segments
    #pragma unroll
    for (int r = 0; r < 8; r++) {
        int i = tid + 256*r;
        int c = i >> 5;
        int x = i & 31;
        bev[(((size_t)b*COUT + c)*YY + y)*XX + xq*XQ + x] = sacc[x*SACCP + c];
    }
}

// ---------------------------------------------------------------------------
extern "C" void kernel_launch(void* const* d_in, const int* in_sizes, int n_in,
                              void* d_out, int out_size) {
    const float* img  = (const float*)d_in[0];  // (4,6,256,16,44)
    const float* c2e  = (const float*)d_in[1];  // (4,6,4,4)
    const float* Kin  = (const float*)d_in[2];  // (4,6,3,3)
    const float* w    = (const float*)d_in[3];  // (123,256)
    const float* bias = (const float*)d_in[4];  // (123,)
    float* out       = (float*)d_out;
    float* depth_out = out + BEV_SIZE;          // outputs: [bev | depth]

    const int smem_bytes = 2*BUFW*4;            // 139264 B
    cudaFuncSetAttribute(gemm_mma, cudaFuncAttributeMaxDynamicSharedMemorySize, smem_bytes);

    gemm_mma<<<NPIX/TILE_M, 512, smem_bytes>>>(img, w, bias, depth_out);
    bev_kernel<<<Bc*YY*4, 256>>>(c2e, Kin, depth_out, out);
}